// round 3
// baseline (speedup 1.0000x reference)
#include <cuda_runtime.h>
#include <cstdint>

#define NB   32
#define H    1024
#define W    1024
#define BH   73
#define BW   73
#define BS   14          // block stride = 16 - 3 + 1
#define TOTAL (NB*BH*BW) // 170528
#define CHUNK 1024
#define NCHUNKS ((TOTAL + CHUNK - 1) / CHUNK)  // 167

__device__ int g_flags[TOTAL];
__device__ int g_csum[NCHUNKS];
__device__ int g_coff[NCHUNKS];

// ---------------------------------------------------------------------------
// Kernel 1: fused pad + 16x16/stride14 max-pool + threshold -> g_flags.
// One CTA per (n, by) strip. Early-out after 2 rows when all 73 windows are
// already above threshold (overwhelmingly likely for U(0,1) input).
// ---------------------------------------------------------------------------
__global__ __launch_bounds__(256) void pool_kernel(const float* __restrict__ mask) {
    const int cta = blockIdx.x;          // n*BH + by
    const int n  = cta / BH;
    const int by = cta % BH;
    const int t  = threadIdx.x;          // 256 threads

    __shared__ float colmax[W];
    __shared__ int undecided;

    const float4* base = (const float4*)(mask + (size_t)n * H * W);
    const int row0 = by * BS - 1;        // first (padded->real) row of window

    float4 m = make_float4(0.f, 0.f, 0.f, 0.f);

    // rows r = 0,1 (real rows row0, row0+1; row0 may be -1 => zero pad)
#pragma unroll
    for (int r = 0; r < 2; r++) {
        int real = row0 + r;
        if (real >= 0) {
            float4 v = base[real * (W / 4) + t];
            m.x = fmaxf(m.x, v.x); m.y = fmaxf(m.y, v.y);
            m.z = fmaxf(m.z, v.z); m.w = fmaxf(m.w, v.w);
        }
    }
    colmax[4 * t + 0] = m.x; colmax[4 * t + 1] = m.y;
    colmax[4 * t + 2] = m.z; colmax[4 * t + 3] = m.w;
    if (t == 0) undecided = 0;
    __syncthreads();

    if (t < BW) {
        float mx = 0.f;
        int c0 = t * BS - 1;
#pragma unroll
        for (int k = 0; k < 16; k++) {
            int c = c0 + k;
            if (c >= 0 && c < W) mx = fmaxf(mx, colmax[c]);
        }
        if (!(mx > 0.5f)) atomicAdd(&undecided, 1);
    }
    __syncthreads();

    if (undecided == 0) {                 // fast path: every window active
        if (t < BW) g_flags[cta * BW + t] = 1;
        return;
    }

    // slow path: accumulate remaining 14 rows (always fully in range)
    for (int r = 2; r < 16; r++) {
        int real = row0 + r;              // by<=72 => real <= 1022
        float4 v = base[real * (W / 4) + t];
        m.x = fmaxf(m.x, v.x); m.y = fmaxf(m.y, v.y);
        m.z = fmaxf(m.z, v.z); m.w = fmaxf(m.w, v.w);
    }
    __syncthreads();                      // WAR on colmax
    colmax[4 * t + 0] = m.x; colmax[4 * t + 1] = m.y;
    colmax[4 * t + 2] = m.z; colmax[4 * t + 3] = m.w;
    __syncthreads();

    if (t < BW) {
        float mx = 0.f;
        int c0 = t * BS - 1;
#pragma unroll
        for (int k = 0; k < 16; k++) {
            int c = c0 + k;
            if (c >= 0 && c < W) mx = fmaxf(mx, colmax[c]);
        }
        g_flags[cta * BW + t] = (mx > 0.5f) ? 1 : 0;
    }
}

// ---------------------------------------------------------------------------
// Kernel 2: fill every output row with the fill triple (NB, BH, BW) as FLOATS.
// Scatter later overwrites rows [0, count). Coalesced writes.
// ---------------------------------------------------------------------------
__global__ void fill_kernel(float* __restrict__ out) {
    int j = blockIdx.x * blockDim.x + threadIdx.x;
    if (j < 3 * TOTAL) out[j] = (j % 3 == 0) ? (float)NB : (float)BH;  // BH==BW
}

// ---------------------------------------------------------------------------
// Kernel 3: per-chunk flag sums.
// ---------------------------------------------------------------------------
__global__ __launch_bounds__(256) void chunksum_kernel() {
    __shared__ int red[256];
    int b = blockIdx.x;
    int base = b * CHUNK;
    int s = 0;
    for (int i = threadIdx.x; i < CHUNK; i += 256) {
        int g = base + i;
        if (g < TOTAL) s += g_flags[g];
    }
    red[threadIdx.x] = s;
    __syncthreads();
    for (int off = 128; off > 0; off >>= 1) {
        if (threadIdx.x < off) red[threadIdx.x] += red[threadIdx.x + off];
        __syncthreads();
    }
    if (threadIdx.x == 0) g_csum[b] = red[0];
}

// ---------------------------------------------------------------------------
// Kernel 4: exclusive scan of chunk sums (tiny, serial) + write count (float).
// count_idx < 0 => no count slot in the output buffer.
// ---------------------------------------------------------------------------
__global__ void scan_kernel(float* __restrict__ out, int count_idx) {
    if (threadIdx.x == 0 && blockIdx.x == 0) {
        int acc = 0;
        for (int i = 0; i < NCHUNKS; i++) {
            g_coff[i] = acc;
            acc += g_csum[i];
        }
        if (count_idx >= 0) out[count_idx] = (float)acc;
    }
}

// ---------------------------------------------------------------------------
// Kernel 5: scatter active indices to their stable prefix positions (floats).
// One CTA per chunk; 4 elems/thread + block scan.
// ---------------------------------------------------------------------------
__global__ __launch_bounds__(256) void scatter_kernel(float* __restrict__ out) {
    __shared__ int sc[256];
    int b = blockIdx.x;
    int t = threadIdx.x;
    int g0 = b * CHUNK + t * 4;

    int f[4];
    int local = 0;
#pragma unroll
    for (int i = 0; i < 4; i++) {
        f[i] = (g0 + i < TOTAL) ? g_flags[g0 + i] : 0;
        local += f[i];
    }

    sc[t] = local;
    __syncthreads();
    // Hillis-Steele inclusive scan
    for (int off = 1; off < 256; off <<= 1) {
        int v = (t >= off) ? sc[t - off] : 0;
        __syncthreads();
        sc[t] += v;
        __syncthreads();
    }
    int pos = g_coff[b] + sc[t] - local;   // exclusive prefix

#pragma unroll
    for (int i = 0; i < 4; i++) {
        if (f[i]) {
            int g  = g0 + i;
            int i0 = g / (BH * BW);
            int r  = g - i0 * (BH * BW);
            int i1 = r / BW;
            int i2 = r - i1 * BW;
            out[3 * pos + 0] = (float)i0;
            out[3 * pos + 1] = (float)i1;
            out[3 * pos + 2] = (float)i2;
            pos++;
        }
    }
}

extern "C" void kernel_launch(void* const* d_in, const int* in_sizes, int n_in,
                              void* d_out, int out_size) {
    const float* mask = (const float*)d_in[0];
    float* out = (float*)d_out;

    // count slot exists only if the buffer is larger than the index matrix
    int count_idx = (out_size > 3 * TOTAL) ? (out_size - 1) : -1;

    pool_kernel<<<NB * BH, 256>>>(mask);
    fill_kernel<<<(3 * TOTAL + 255) / 256, 256>>>(out);
    chunksum_kernel<<<NCHUNKS, 256>>>();
    scan_kernel<<<1, 32>>>(out, count_idx);
    scatter_kernel<<<NCHUNKS, 256>>>(out);
}

// round 4
// speedup vs baseline: 1.7004x; 1.7004x over previous
#include <cuda_runtime.h>
#include <cstdint>

#define NB   32
#define H    1024
#define W    1024
#define BH   73
#define BW   73
#define BS   14                  // block stride = 16 - 3 + 1
#define NROWS (NB*BH)            // 2336 (flag rows / chunks)
#define TOTAL (NB*BH*BW)         // 170528

__device__ int g_flags[TOTAL];
__device__ int g_csum[NROWS];
__device__ int g_coff[NROWS];
__device__ int g_count;

// ---------------------------------------------------------------------------
// Kernel 1: fused pad + 16x16/stride14 max-pool + threshold -> flags + row sums.
// One CTA per (n, by) strip. Fast path: read ONE in-range row (by*14); a
// window is decided-active unless all 16 of its samples in that row are
// <= 0.5 (p = 2^-16). ~3 strips total fall to the 16-row slow path.
// ---------------------------------------------------------------------------
__global__ __launch_bounds__(256) void pool_kernel(const float* __restrict__ mask) {
    const int cta = blockIdx.x;          // n*BH + by
    const int n  = cta / BH;
    const int by = cta % BH;
    const int t  = threadIdx.x;          // 256 threads

    __shared__ float colmax[W];

    const float4* base = (const float4*)(mask + (size_t)n * H * W);
    const int rm = by * BS;              // probe row, always in [0, 1008]

    float4 v = base[rm * (W / 4) + t];
    colmax[4 * t + 0] = v.x; colmax[4 * t + 1] = v.y;
    colmax[4 * t + 2] = v.z; colmax[4 * t + 3] = v.w;
    __syncthreads();

    int flag = 0;
    if (t < BW) {
        float mx = 0.f;
        int c0 = t * BS - 1;
#pragma unroll
        for (int k = 0; k < 16; k++) {
            int c = c0 + k;
            if (c >= 0 && c < W) mx = fmaxf(mx, colmax[c]);
        }
        flag = (mx > 0.5f) ? 1 : 0;
    }
    int und = __syncthreads_count(t < BW && !flag);

    if (und == 0) {                      // fast path: every window active
        if (t < BW) g_flags[cta * BW + t] = 1;
        if (t == 0) g_csum[cta] = BW;
        return;
    }

    // slow path: full 16-row window max (row0 may be -1 => zero pad)
    const int row0 = by * BS - 1;        // row0+15 <= 1022, always < H
    float4 m = v;                        // probe row already loaded
#pragma unroll
    for (int r = 0; r < 16; r++) {
        int real = row0 + r;
        if (real == rm || real < 0) continue;
        float4 u = base[real * (W / 4) + t];
        m.x = fmaxf(m.x, u.x); m.y = fmaxf(m.y, u.y);
        m.z = fmaxf(m.z, u.z); m.w = fmaxf(m.w, u.w);
    }
    __syncthreads();                     // all reads of colmax done
    colmax[4 * t + 0] = m.x; colmax[4 * t + 1] = m.y;
    colmax[4 * t + 2] = m.z; colmax[4 * t + 3] = m.w;
    __syncthreads();

    flag = 0;
    if (t < BW) {
        float mx = 0.f;
        int c0 = t * BS - 1;
#pragma unroll
        for (int k = 0; k < 16; k++) {
            int c = c0 + k;
            if (c >= 0 && c < W) mx = fmaxf(mx, colmax[c]);
        }
        flag = (mx > 0.5f) ? 1 : 0;
        g_flags[cta * BW + t] = flag;
    }
    int cnt = __syncthreads_count(t < BW && flag);
    if (t == 0) g_csum[cta] = cnt;
}

// ---------------------------------------------------------------------------
// Kernel 2: parallel exclusive scan of 2336 row sums (1 CTA, 256 threads).
// Thread-blocked serial sums + warp-shuffle block scan. Writes g_coff,
// g_count, and the float count slot.
// ---------------------------------------------------------------------------
#define PER 10   // ceil(2336/256) = 10 (2560 slots, tail zero-padded)

__global__ __launch_bounds__(256) void scan_kernel(float* __restrict__ out,
                                                   int count_idx) {
    const int t = threadIdx.x;
    const int lane = t & 31, w = t >> 5;
    __shared__ int wtot[8];
    __shared__ int woff[9];

    int local[PER];
    int s = 0;
    int base = t * PER;
#pragma unroll
    for (int i = 0; i < PER; i++) {
        int g = base + i;
        local[i] = (g < NROWS) ? g_csum[g] : 0;
        s += local[i];
    }

    // warp inclusive scan of per-thread sums
    int x = s;
#pragma unroll
    for (int off = 1; off < 32; off <<= 1) {
        int y = __shfl_up_sync(0xffffffffu, x, off);
        if (lane >= off) x += y;
    }
    if (lane == 31) wtot[w] = x;
    __syncthreads();
    if (t == 0) {
        int acc = 0;
        for (int i = 0; i < 8; i++) { woff[i] = acc; acc += wtot[i]; }
        woff[8] = acc;                   // grand total
        g_count = acc;
        if (count_idx >= 0) out[count_idx] = (float)acc;
    }
    __syncthreads();

    int excl = woff[w] + x - s;          // exclusive prefix of this thread
#pragma unroll
    for (int i = 0; i < PER; i++) {
        int g = base + i;
        if (g < NROWS) g_coff[g] = excl;
        excl += local[i];
    }
}

// ---------------------------------------------------------------------------
// Kernel 3: scatter active indices to their stable prefix positions (floats).
// One CTA per flag row (73 flags); warp-shuffle block scan.
// ---------------------------------------------------------------------------
__global__ __launch_bounds__(128) void scatter_kernel(float* __restrict__ out) {
    const int row = blockIdx.x;          // n*BH + by
    const int t = threadIdx.x;
    const int lane = t & 31, w = t >> 5;
    __shared__ int wtot[4];

    int f = (t < BW) ? g_flags[row * BW + t] : 0;

    int x = f;
#pragma unroll
    for (int off = 1; off < 32; off <<= 1) {
        int y = __shfl_up_sync(0xffffffffu, x, off);
        if (lane >= off) x += y;
    }
    if (lane == 31) wtot[w] = x;
    __syncthreads();
    int woff = 0;
#pragma unroll
    for (int i = 0; i < 4; i++) if (i < w) woff += wtot[i];

    if (f) {
        int pos = g_coff[row] + woff + x - f;
        int i0 = row / BH;
        int i1 = row - i0 * BH;
        out[3 * pos + 0] = (float)i0;
        out[3 * pos + 1] = (float)i1;
        out[3 * pos + 2] = (float)t;
    }
}

// ---------------------------------------------------------------------------
// Kernel 4: fill only the tail rows [count, TOTAL) with (NB, BH, BW).
// Normally count ~= TOTAL so this writes (almost) nothing.
// ---------------------------------------------------------------------------
__global__ __launch_bounds__(256) void tailfill_kernel(float* __restrict__ out) {
    int j = blockIdx.x * blockDim.x + threadIdx.x;
    if (j < TOTAL && j >= g_count) {
        out[3 * j + 0] = (float)NB;
        out[3 * j + 1] = (float)BH;
        out[3 * j + 2] = (float)BW;
    }
}

extern "C" void kernel_launch(void* const* d_in, const int* in_sizes, int n_in,
                              void* d_out, int out_size) {
    const float* mask = (const float*)d_in[0];
    float* out = (float*)d_out;

    int count_idx = (out_size > 3 * TOTAL) ? (out_size - 1) : -1;

    pool_kernel<<<NROWS, 256>>>(mask);
    scan_kernel<<<1, 256>>>(out, count_idx);
    scatter_kernel<<<NROWS, 128>>>(out);
    tailfill_kernel<<<(TOTAL + 255) / 256, 256>>>(out);
}

// round 5
// speedup vs baseline: 1.9725x; 1.1600x over previous
#include <cuda_runtime.h>
#include <cstdint>

#define NB   32
#define H    1024
#define W    1024
#define BH   73
#define BW   73
#define BS   14                  // block stride = 16 - 3 + 1
#define NROWS (NB*BH)            // 2336 flag rows
#define TOTAL (NB*BH*BW)         // 170528

__device__ unsigned g_bits[NROWS * 3];   // 73-bit mask per row (slow path only)
__device__ int g_csum[NROWS];
__device__ int g_coff[NROWS];
__device__ int g_count;

// ---------------------------------------------------------------------------
// Kernel 1: fused pad + 16x16/stride14 max-pool + threshold.
// One CTA per (n, by) strip. Fast path: read ONE in-range row (by*14); a
// window is decided-active unless all 16 of its samples in that row are
// <= 0.5 (p = 2^-16) -> ~3 strips total take the 16-row slow path.
// Fast path writes only g_csum[row] = 73. Slow path writes 3 bitmask words.
// ---------------------------------------------------------------------------
__global__ __launch_bounds__(256) void pool_kernel(const float* __restrict__ mask) {
    const int cta = blockIdx.x;          // n*BH + by
    const int n  = cta / BH;
    const int by = cta % BH;
    const int t  = threadIdx.x;          // 256 threads

    __shared__ float colmax[W];

    const float4* base = (const float4*)(mask + (size_t)n * H * W);
    const int rm = by * BS;              // probe row, always in [0, 1008]

    float4 v = base[rm * (W / 4) + t];
    colmax[4 * t + 0] = v.x; colmax[4 * t + 1] = v.y;
    colmax[4 * t + 2] = v.z; colmax[4 * t + 3] = v.w;
    __syncthreads();

    int flag = 0;
    if (t < BW) {
        float mx = 0.f;
        int c0 = t * BS - 1;
#pragma unroll
        for (int k = 0; k < 16; k++) {
            int c = c0 + k;
            if (c >= 0 && c < W) mx = fmaxf(mx, colmax[c]);
        }
        flag = (mx > 0.5f) ? 1 : 0;
    }
    int und = __syncthreads_count(t < BW && !flag);

    if (und == 0) {                      // fast path: every window active
        if (t == 0) g_csum[cta] = BW;
        return;
    }

    // slow path: full 16-row window max (row0 may be -1 => zero pad)
    const int row0 = by * BS - 1;        // row0+15 <= 1022, always < H
    float4 m = v;                        // probe row already loaded
#pragma unroll
    for (int r = 0; r < 16; r++) {
        int real = row0 + r;
        if (real == rm || real < 0) continue;
        float4 u = base[real * (W / 4) + t];
        m.x = fmaxf(m.x, u.x); m.y = fmaxf(m.y, u.y);
        m.z = fmaxf(m.z, u.z); m.w = fmaxf(m.w, u.w);
    }
    __syncthreads();                     // all reads of colmax done
    colmax[4 * t + 0] = m.x; colmax[4 * t + 1] = m.y;
    colmax[4 * t + 2] = m.z; colmax[4 * t + 3] = m.w;
    __syncthreads();

    flag = 0;
    if (t < BW) {
        float mx = 0.f;
        int c0 = t * BS - 1;
#pragma unroll
        for (int k = 0; k < 16; k++) {
            int c = c0 + k;
            if (c >= 0 && c < W) mx = fmaxf(mx, colmax[c]);
        }
        flag = (mx > 0.5f) ? 1 : 0;
    }
    unsigned bal = __ballot_sync(0xffffffffu, flag);   // flag==0 for t>=73
    int wid = t >> 5;
    if ((t & 31) == 0 && wid < 3) g_bits[cta * 3 + wid] = bal;

    int cnt = __syncthreads_count(flag);
    if (t == 0) g_csum[cta] = cnt;
}

// ---------------------------------------------------------------------------
// Kernel 2: parallel exclusive scan of 2336 row sums (1 CTA, 256 threads).
// ---------------------------------------------------------------------------
#define PER 10   // 256*10 = 2560 >= 2336

__global__ __launch_bounds__(256) void scan_kernel(float* __restrict__ out,
                                                   int count_idx) {
    const int t = threadIdx.x;
    const int lane = t & 31, w = t >> 5;
    __shared__ int wtot[8];
    __shared__ int woff[8];

    int local[PER];
    int s = 0;
    int base = t * PER;
#pragma unroll
    for (int i = 0; i < PER; i++) {
        int g = base + i;
        local[i] = (g < NROWS) ? g_csum[g] : 0;
        s += local[i];
    }

    int x = s;                            // warp inclusive scan
#pragma unroll
    for (int off = 1; off < 32; off <<= 1) {
        int y = __shfl_up_sync(0xffffffffu, x, off);
        if (lane >= off) x += y;
    }
    if (lane == 31) wtot[w] = x;
    __syncthreads();
    if (t == 0) {
        int acc = 0;
        for (int i = 0; i < 8; i++) { woff[i] = acc; acc += wtot[i]; }
        g_count = acc;
        if (count_idx >= 0) out[count_idx] = (float)acc;
    }
    __syncthreads();

    int excl = woff[w] + x - s;
#pragma unroll
    for (int i = 0; i < PER; i++) {
        int g = base + i;
        if (g < NROWS) g_coff[g] = excl;
        excl += local[i];
    }
}

// ---------------------------------------------------------------------------
// Kernel 3: scatter. One CTA (128 thr) per row. Fast rows (csum==73) write
// their 73 active triples directly. Slow rows use the bitmask + popc prefix;
// inactive elements write the fill triple at count + inactive_rank (inactive
// ranks are globally contiguous), so no separate tail-fill pass is needed.
// ---------------------------------------------------------------------------
__global__ __launch_bounds__(128) void scatter_kernel(float* __restrict__ out) {
    const int row = blockIdx.x;          // n*BH + by
    const int t = threadIdx.x;
    if (t >= BW) return;

    const int cnt = g_csum[row];
    const int off = g_coff[row];
    const int i0 = row / BH;
    const int i1 = row - i0 * BH;

    if (cnt == BW) {                     // fast path: all 73 active
        int pos = off + t;
        out[3 * pos + 0] = (float)i0;
        out[3 * pos + 1] = (float)i1;
        out[3 * pos + 2] = (float)t;
        return;
    }

    unsigned w0 = g_bits[row * 3 + 0];
    unsigned w1 = g_bits[row * 3 + 1];
    unsigned w2 = g_bits[row * 3 + 2];
    unsigned lmask = (1u << (t & 31)) - 1u;

    int below, f;
    if (t < 32)      { below = __popc(w0 & lmask);                       f = (w0 >> t) & 1; }
    else if (t < 64) { below = __popc(w0) + __popc(w1 & lmask);          f = (w1 >> (t - 32)) & 1; }
    else             { below = __popc(w0) + __popc(w1) + __popc(w2 & lmask); f = (w2 >> (t - 64)) & 1; }

    if (f) {
        int pos = off + below;
        out[3 * pos + 0] = (float)i0;
        out[3 * pos + 1] = (float)i1;
        out[3 * pos + 2] = (float)t;
    } else {
        int g = row * BW + t;
        int pos = g_count + (g - (off + below));   // contiguous inactive ranks
        out[3 * pos + 0] = (float)NB;
        out[3 * pos + 1] = (float)BH;
        out[3 * pos + 2] = (float)BW;
    }
}

extern "C" void kernel_launch(void* const* d_in, const int* in_sizes, int n_in,
                              void* d_out, int out_size) {
    const float* mask = (const float*)d_in[0];
    float* out = (float*)d_out;

    int count_idx = (out_size > 3 * TOTAL) ? (out_size - 1) : -1;

    pool_kernel<<<NROWS, 256>>>(mask);
    scan_kernel<<<1, 256>>>(out, count_idx);
    scatter_kernel<<<NROWS, 128>>>(out);
}